// round 1
// baseline (speedup 1.0000x reference)
#include <cuda_runtime.h>
#include <math.h>

#define Nn 1024
#define Ee 4096
#define NB 64
#define NKB 16   // Nn / NB

// ---------------- scratch (static device globals; no allocation) ----------------
__device__ int   d_heads[Ee], d_tails[Ee];
__device__ float d_s[Ee], d_sigma[Ee], d_w0[Ee], d_w1[Ee], d_w2[Ee];
__device__ float d_u[4][Nn];
__device__ float d_r[Nn], d_yv[Nn], d_z[Nn];
__device__ float d_L [Nn * Nn];
__device__ float d_L2[Nn * Nn];
__device__ float d_S [Nn * Nn];
__device__ float d_Ht[(size_t)Ee * Nn];        // H transposed: edge-major [E][N]
__device__ float d_Linv[NKB * NB * NB];        // per-panel inverse of diag Cholesky block

// ---------------- small kernels ----------------
__global__ void k_extract(const float* __restrict__ B) {
    int idx = blockIdx.x * blockDim.x + threadIdx.x;
    if (idx >= Nn * Ee) return;
    float v = B[idx];
    int e = idx % Ee, n = idx / Ee;
    if (v > 0.5f)       d_heads[e] = n;
    else if (v < -0.5f) d_tails[e] = n;
}

__global__ void k_setup(const float* __restrict__ F, const float* __restrict__ Cu,
                        const float* __restrict__ Cx, const float* __restrict__ s0) {
    int e = blockIdx.x * blockDim.x + threadIdx.x;
    if (e >= Ee) return;
    size_t d = (size_t)e * Ee + e;
    float f = F[d];
    d_s[e] = f * s0[e];
    d_sigma[e] = f * f * Cx[d] + Cu[d];
}

__global__ void k_zeroL() {
    int i = blockIdx.x * blockDim.x + threadIdx.x;
    if (i < Nn * Nn) d_L[i] = 0.f;
}

__global__ void k_assemble() {
    int e = blockIdx.x * blockDim.x + threadIdx.x;
    if (e >= Ee) return;
    float se = d_s[e];
    int h = d_heads[e], t = d_tails[e];
    atomicAdd(&d_L[h * Nn + h],  se);
    atomicAdd(&d_L[t * Nn + t],  se);
    atomicAdd(&d_L[h * Nn + t], -se);
    atomicAdd(&d_L[t * Nn + h], -se);
}

__global__ void k_copyq(const float* __restrict__ q) {
    int n = blockIdx.x * blockDim.x + threadIdx.x;
    if (n < Nn) d_u[0][n] = q[n];
}

// d_u[mo] = L * d_u[mi]   (one block per row)
__global__ void k_matvec(int mi, int mo) {
    int row = blockIdx.x, t = threadIdx.x;
    const float* Lr = &d_L[(size_t)row * Nn];
    float acc = 0.f;
    for (int j = t; j < Nn; j += 128) acc += Lr[j] * d_u[mi][j];
    for (int off = 16; off; off >>= 1) acc += __shfl_down_sync(0xffffffffu, acc, off);
    __shared__ float ws[4];
    if ((t & 31) == 0) ws[t >> 5] = acc;
    __syncthreads();
    if (t == 0) d_u[mo][row] = ws[0] + ws[1] + ws[2] + ws[3];
}

__global__ void k_VW(const float* __restrict__ a) {
    int e = blockIdx.x * blockDim.x + threadIdx.x;
    if (e >= Ee) return;
    int h = d_heads[e], t = d_tails[e];
    float V0 = d_u[0][h] - d_u[0][t];
    float V1 = d_u[1][h] - d_u[1][t];
    float V2 = d_u[2][h] - d_u[2][t];
    float a1 = a[1], a2 = a[2], a3 = a[3];
    d_w0[e] = a1 * V0 + a2 * V1 + a3 * V2;
    d_w1[e] = a2 * V0 + a3 * V1;
    d_w2[e] = a3 * V0;
}

__global__ void k_polyr(const float* __restrict__ a, const float* __restrict__ y) {
    int n = blockIdx.x * blockDim.x + threadIdx.x;
    if (n >= Nn) return;
    d_r[n] = y[n] - (a[0] * d_u[0][n] + a[1] * d_u[1][n] + a[2] * d_u[2][n] + a[3] * d_u[3][n]);
}

// ---------------- L2 = L * L^T (L symmetric => L^2) ----------------
__global__ void k_gemmL2() {
    __shared__ float As[16][65], Bs[16][65];
    int I = blockIdx.y * 64, J = blockIdx.x * 64;
    int t = threadIdx.x;
    int lm = t >> 2, lk = (t & 3) << 2;
    int ty = t >> 4, tx = t & 15;
    float acc[4][4] = {};
    for (int k0 = 0; k0 < Nn; k0 += 16) {
        float4 av = *(const float4*)&d_L[(size_t)(I + lm) * Nn + k0 + lk];
        float4 bv = *(const float4*)&d_L[(size_t)(J + lm) * Nn + k0 + lk];
        As[lk + 0][lm] = av.x; As[lk + 1][lm] = av.y; As[lk + 2][lm] = av.z; As[lk + 3][lm] = av.w;
        Bs[lk + 0][lm] = bv.x; Bs[lk + 1][lm] = bv.y; Bs[lk + 2][lm] = bv.z; Bs[lk + 3][lm] = bv.w;
        __syncthreads();
#pragma unroll
        for (int kk = 0; kk < 16; kk++) {
            float ar[4], br[4];
#pragma unroll
            for (int i = 0; i < 4; i++) { ar[i] = As[kk][ty * 4 + i]; br[i] = Bs[kk][tx * 4 + i]; }
#pragma unroll
            for (int i = 0; i < 4; i++)
#pragma unroll
                for (int j = 0; j < 4; j++) acc[i][j] += ar[i] * br[j];
        }
        __syncthreads();
    }
#pragma unroll
    for (int i = 0; i < 4; i++)
#pragma unroll
        for (int j = 0; j < 4; j++)
            d_L2[(size_t)(I + ty * 4 + i) * Nn + J + tx * 4 + j] = acc[i][j];
}

// ---------------- Ht[e, :] = w0*b_e + w1*(L[h,:]-L[t,:]) + w2*(L2[h,:]-L2[t,:]) ----------------
__global__ void k_buildHt() {
    int e = blockIdx.x;
    int h = d_heads[e], tt = d_tails[e];
    float w0 = d_w0[e], w1 = d_w1[e], w2 = d_w2[e];
    const float* Lh  = &d_L [(size_t)h  * Nn];
    const float* Lt  = &d_L [(size_t)tt * Nn];
    const float* L2h = &d_L2[(size_t)h  * Nn];
    const float* L2t = &d_L2[(size_t)tt * Nn];
    float* out = &d_Ht[(size_t)e * Nn];
    for (int n = threadIdx.x; n < Nn; n += 256) {
        float v = w1 * (Lh[n] - Lt[n]) + w2 * (L2h[n] - L2t[n]);
        if (n == h)  v += w0;
        if (n == tt) v -= w0;
        out[n] = v;
    }
}

// ---------------- S = H diag(sigma) H^T + C_w  (K = E) ----------------
__global__ void k_gemmS(const float* __restrict__ Cw) {
    __shared__ float As[16][64], Bs[16][64];
    int I = blockIdx.y * 64, J = blockIdx.x * 64;
    int t = threadIdx.x;
    int ldk = t >> 4, ldm = (t & 15) << 2;
    int ty = t >> 4, tx = t & 15;
    float acc[4][4] = {};
    for (int e0 = 0; e0 < Ee; e0 += 16) {
        float sg = d_sigma[e0 + ldk];
        const float* row = &d_Ht[(size_t)(e0 + ldk) * Nn];
        float4 av = *(const float4*)&row[I + ldm];
        float4 bv = *(const float4*)&row[J + ldm];
        av.x *= sg; av.y *= sg; av.z *= sg; av.w *= sg;
        *(float4*)&As[ldk][ldm] = av;
        *(float4*)&Bs[ldk][ldm] = bv;
        __syncthreads();
#pragma unroll
        for (int kk = 0; kk < 16; kk++) {
            float4 a4 = *(const float4*)&As[kk][ty * 4];
            float4 b4 = *(const float4*)&Bs[kk][tx * 4];
            float ar[4] = {a4.x, a4.y, a4.z, a4.w};
            float br[4] = {b4.x, b4.y, b4.z, b4.w};
#pragma unroll
            for (int i = 0; i < 4; i++)
#pragma unroll
                for (int j = 0; j < 4; j++) acc[i][j] += ar[i] * br[j];
        }
        __syncthreads();
    }
#pragma unroll
    for (int i = 0; i < 4; i++)
#pragma unroll
        for (int j = 0; j < 4; j++) {
            size_t idx = (size_t)(I + ty * 4 + i) * Nn + J + tx * 4 + j;
            d_S[idx] = acc[i][j] + Cw[idx];
        }
}

// ---------------- blocked Cholesky (lower, in-place in d_S) ----------------
__global__ void k_potrf(int kblk) {
    int o = kblk * NB;
    __shared__ float A[NB][NB + 1];
    __shared__ float Bi[NB][NB + 1];
    int t = threadIdx.x;   // 64 threads
    for (int j = 0; j < NB; j++) A[j][t] = d_S[(size_t)(o + j) * Nn + o + t];
    __syncthreads();
    for (int j = 0; j < NB; j++) {
        float acc = 0.f;
        if (t >= j) {
            acc = A[t][j];
            for (int m = 0; m < j; m++) acc -= A[t][m] * A[j][m];
        }
        __syncthreads();
        if (t == j) A[j][j] = sqrtf(acc);
        __syncthreads();
        if (t > j) A[t][j] = acc / A[j][j];
        __syncthreads();
    }
    // lower-triangular inverse, one column per thread
    {
        int c = t;
        for (int r2 = 0; r2 < c; r2++) Bi[r2][c] = 0.f;
        for (int r2 = c; r2 < NB; r2++) {
            float v = (r2 == c) ? 1.f : 0.f;
            for (int m = c; m < r2; m++) v -= A[r2][m] * Bi[m][c];
            Bi[r2][c] = v / A[r2][r2];
        }
    }
    __syncthreads();
    for (int j = 0; j < NB; j++) {
        d_S[(size_t)(o + j) * Nn + o + t] = A[j][t];
        d_Linv[kblk * NB * NB + j * NB + t] = Bi[j][t];
    }
}

// panel rows: L21 = A21 * Linv^T (in place)
__global__ void k_trsm(int kblk) {
    int o = kblk * NB;
    int r0 = o + NB + blockIdx.x * NB;
    __shared__ float At[NB][NB + 1], Lv[NB][NB + 1];
    int t = threadIdx.x;
    for (int idx = t; idx < NB * NB; idx += 256) {
        int r = idx >> 6, c = idx & 63;
        At[r][c] = d_S[(size_t)(r0 + r) * Nn + o + c];
        Lv[r][c] = d_Linv[kblk * NB * NB + idx];
    }
    __syncthreads();
    int ty = t >> 4, tx = t & 15;
    float acc[4][4] = {};
    for (int m = 0; m < NB; m++) {
        float ar[4], br[4];
#pragma unroll
        for (int i = 0; i < 4; i++) { ar[i] = At[ty * 4 + i][m]; br[i] = Lv[tx * 4 + i][m]; }
#pragma unroll
        for (int i = 0; i < 4; i++)
#pragma unroll
            for (int j = 0; j < 4; j++) acc[i][j] += ar[i] * br[j];
    }
#pragma unroll
    for (int i = 0; i < 4; i++)
#pragma unroll
        for (int j = 0; j < 4; j++)
            d_S[(size_t)(r0 + ty * 4 + i) * Nn + o + tx * 4 + j] = acc[i][j];
}

// trailing update: A22 -= L21 * L21^T (lower tiles only)
__global__ void k_syrk(int kblk) {
    int bi = blockIdx.y, bj = blockIdx.x;
    if (bi < bj) return;
    int o = kblk * NB;
    int ri = o + NB + bi * NB, rj = o + NB + bj * NB;
    __shared__ float Pi[NB][NB + 1], Pj[NB][NB + 1];
    int t = threadIdx.x;
    for (int idx = t; idx < NB * NB; idx += 256) {
        int r = idx >> 6, c = idx & 63;
        Pi[r][c] = d_S[(size_t)(ri + r) * Nn + o + c];
        Pj[r][c] = d_S[(size_t)(rj + r) * Nn + o + c];
    }
    __syncthreads();
    int ty = t >> 4, tx = t & 15;
    float acc[4][4] = {};
    for (int m = 0; m < NB; m++) {
        float ar[4], br[4];
#pragma unroll
        for (int i = 0; i < 4; i++) { ar[i] = Pi[ty * 4 + i][m]; br[i] = Pj[tx * 4 + i][m]; }
#pragma unroll
        for (int i = 0; i < 4; i++)
#pragma unroll
            for (int j = 0; j < 4; j++) acc[i][j] += ar[i] * br[j];
    }
#pragma unroll
    for (int i = 0; i < 4; i++)
#pragma unroll
        for (int j = 0; j < 4; j++) {
            size_t idx = (size_t)(ri + ty * 4 + i) * Nn + rj + tx * 4 + j;
            d_S[idx] -= acc[i][j];
        }
}

// forward: L y = r (blocked)
__global__ void k_fsolve(int kblk) {
    int o = kblk * NB;
    __shared__ float part[256];
    __shared__ float tv[NB];
    int t = threadIdx.x, i = t & 63, g = t >> 6;
    float acc = 0.f;
    for (int j = g; j < o; j += 4) acc -= d_S[(size_t)(o + i) * Nn + j] * d_yv[j];
    part[t] = acc;
    __syncthreads();
    if (t < NB) tv[t] = d_r[o + t] + part[t] + part[64 + t] + part[128 + t] + part[192 + t];
    __syncthreads();
    if (t < NB) {
        const float* Li = &d_Linv[kblk * NB * NB + t * NB];
        float a2 = 0.f;
        for (int m = 0; m < NB; m++) a2 += Li[m] * tv[m];
        d_yv[o + t] = a2;
    }
}

// backward: L^T z = y (blocked, from last block)
__global__ void k_bsolve(int kblk) {
    int o = kblk * NB;
    __shared__ float part[256];
    __shared__ float tv[NB];
    int t = threadIdx.x, i = t & 63, g = t >> 6;
    float acc = 0.f;
    for (int r = o + NB + g; r < Nn; r += 4) acc -= d_S[(size_t)r * Nn + o + i] * d_z[r];
    part[t] = acc;
    __syncthreads();
    if (t < NB) tv[t] = d_yv[o + t] + part[t] + part[64 + t] + part[128 + t] + part[192 + t];
    __syncthreads();
    if (t < NB) {
        float a2 = 0.f;
        for (int m = 0; m < NB; m++) a2 += d_Linv[kblk * NB * NB + m * NB + t] * tv[m];
        d_z[o + t] = a2;
    }
}

// out[e] = relu(s[e] + sigma[e] * dot(Ht[e,:], z))
__global__ void k_out(float* __restrict__ out) {
    int warp = (blockIdx.x << 3) + (threadIdx.x >> 5);
    int lane = threadIdx.x & 31;
    if (warp >= Ee) return;
    const float* row = &d_Ht[(size_t)warp * Nn];
    float acc = 0.f;
    for (int n = lane; n < Nn; n += 32) acc += row[n] * d_z[n];
    for (int off = 16; off; off >>= 1) acc += __shfl_down_sync(0xffffffffu, acc, off);
    if (lane == 0) {
        float v = d_s[warp] + d_sigma[warp] * acc;
        out[warp] = fmaxf(v, 0.f);
    }
}

// ---------------- launch ----------------
extern "C" void kernel_launch(void* const* d_in, const int* in_sizes, int n_in,
                              void* d_out, int out_size) {
    (void)in_sizes; (void)n_in; (void)out_size;
    const float* F  = (const float*)d_in[0];
    const float* B  = (const float*)d_in[1];
    const float* Cu = (const float*)d_in[2];
    const float* Cw = (const float*)d_in[3];
    const float* Cx = (const float*)d_in[4];
    const float* s0 = (const float*)d_in[5];
    const float* a  = (const float*)d_in[6];
    const float* q  = (const float*)d_in[7];
    const float* y  = (const float*)d_in[8];
    float* out = (float*)d_out;

    k_extract<<<(Nn * Ee + 255) / 256, 256>>>(B);
    k_setup<<<(Ee + 255) / 256, 256>>>(F, Cu, Cx, s0);
    k_zeroL<<<(Nn * Nn + 255) / 256, 256>>>();
    k_assemble<<<(Ee + 255) / 256, 256>>>();
    k_copyq<<<4, 256>>>(q);
    k_matvec<<<Nn, 128>>>(0, 1);
    k_matvec<<<Nn, 128>>>(1, 2);
    k_matvec<<<Nn, 128>>>(2, 3);
    k_VW<<<(Ee + 255) / 256, 256>>>(a);
    k_polyr<<<4, 256>>>(a, y);
    k_gemmL2<<<dim3(16, 16), 256>>>();
    k_buildHt<<<Ee, 256>>>();
    k_gemmS<<<dim3(16, 16), 256>>>(Cw);

    for (int k = 0; k < NKB; k++) {
        k_potrf<<<1, 64>>>(k);
        int rb = (Nn - (k + 1) * NB) / NB;
        if (rb > 0) {
            k_trsm<<<rb, 256>>>(k);
            k_syrk<<<dim3(rb, rb), 256>>>(k);
        }
    }
    for (int k = 0; k < NKB; k++)  k_fsolve<<<1, 256>>>(k);
    for (int k = NKB - 1; k >= 0; k--) k_bsolve<<<1, 256>>>(k);

    k_out<<<Ee / 8, 256>>>(out);
}

// round 2
// speedup vs baseline: 1.1260x; 1.1260x over previous
#include <cuda_runtime.h>
#include <math.h>

#define Nn 1024
#define Ee 4096
#define NB 64
#define NKB 16   // Nn / NB

// ---------------- scratch (static device globals; no allocation) ----------------
__device__ int   d_heads[Ee], d_tails[Ee];
__device__ float d_s[Ee], d_sigma[Ee], d_w0[Ee], d_w1[Ee], d_w2[Ee];
__device__ float d_u[4][Nn];
__device__ float d_r[Nn], d_yv[Nn], d_z[Nn];
__device__ float d_L [Nn * Nn];
__device__ float d_L2[Nn * Nn];
__device__ float d_S [Nn * Nn];
__device__ float d_Ht[(size_t)Ee * Nn];        // H transposed: edge-major [E][N]
__device__ float d_Linv[NKB * NB * NB];        // per-panel inverse of diag Cholesky block

// ---------------- small kernels ----------------
__global__ void k_extract(const float* __restrict__ B) {
    int idx = blockIdx.x * blockDim.x + threadIdx.x;
    if (idx >= Nn * Ee) return;
    float v = B[idx];
    int e = idx % Ee, n = idx / Ee;
    if (v > 0.5f)       d_heads[e] = n;
    else if (v < -0.5f) d_tails[e] = n;
}

// fused: zero L, diag setup, copy q
__global__ void k_init(const float* __restrict__ F, const float* __restrict__ Cu,
                       const float* __restrict__ Cx, const float* __restrict__ s0,
                       const float* __restrict__ q) {
    int i = blockIdx.x * blockDim.x + threadIdx.x;
    if (i < Nn * Nn) d_L[i] = 0.f;
    if (i < Ee) {
        size_t d = (size_t)i * Ee + i;
        float f = F[d];
        d_s[i] = f * s0[i];
        d_sigma[i] = f * f * Cx[d] + Cu[d];
    }
    if (i < Nn) d_u[0][i] = q[i];
}

__global__ void k_assemble() {
    int e = blockIdx.x * blockDim.x + threadIdx.x;
    if (e >= Ee) return;
    float se = d_s[e];
    int h = d_heads[e], t = d_tails[e];
    atomicAdd(&d_L[h * Nn + h],  se);
    atomicAdd(&d_L[t * Nn + t],  se);
    atomicAdd(&d_L[h * Nn + t], -se);
    atomicAdd(&d_L[t * Nn + h], -se);
}

// d_u[mo] = L * d_u[mi]   (one block per row)
__global__ void k_matvec(int mi, int mo) {
    int row = blockIdx.x, t = threadIdx.x;
    const float* Lr = &d_L[(size_t)row * Nn];
    float acc = 0.f;
    for (int j = t; j < Nn; j += 128) acc += Lr[j] * d_u[mi][j];
    for (int off = 16; off; off >>= 1) acc += __shfl_down_sync(0xffffffffu, acc, off);
    __shared__ float ws[4];
    if ((t & 31) == 0) ws[t >> 5] = acc;
    __syncthreads();
    if (t == 0) d_u[mo][row] = ws[0] + ws[1] + ws[2] + ws[3];
}

// fused: edge weights w0..w2 and residual r = y - poly
__global__ void k_VWpoly(const float* __restrict__ a, const float* __restrict__ y) {
    int e = blockIdx.x * blockDim.x + threadIdx.x;
    if (e < Ee) {
        int h = d_heads[e], t = d_tails[e];
        float V0 = d_u[0][h] - d_u[0][t];
        float V1 = d_u[1][h] - d_u[1][t];
        float V2 = d_u[2][h] - d_u[2][t];
        float a1 = a[1], a2 = a[2], a3 = a[3];
        d_w0[e] = a1 * V0 + a2 * V1 + a3 * V2;
        d_w1[e] = a2 * V0 + a3 * V1;
        d_w2[e] = a3 * V0;
    }
    if (e < Nn) {
        d_r[e] = y[e] - (a[0] * d_u[0][e] + a[1] * d_u[1][e] + a[2] * d_u[2][e] + a[3] * d_u[3][e]);
    }
}

// ---------------- L2 = L * L^T (symmetric output; compute lower, mirror) ----------------
__global__ void k_gemmL2() {
    if (blockIdx.y < blockIdx.x) return;
    __shared__ float As[16][65], Bs[16][65];
    __shared__ float Ts[64][65];
    int I = blockIdx.y * 64, J = blockIdx.x * 64;
    int t = threadIdx.x;
    int lm = t >> 2, lk = (t & 3) << 2;
    int ty = t >> 4, tx = t & 15;
    float acc[4][4] = {};
    for (int k0 = 0; k0 < Nn; k0 += 16) {
        float4 av = *(const float4*)&d_L[(size_t)(I + lm) * Nn + k0 + lk];
        float4 bv = *(const float4*)&d_L[(size_t)(J + lm) * Nn + k0 + lk];
        As[lk + 0][lm] = av.x; As[lk + 1][lm] = av.y; As[lk + 2][lm] = av.z; As[lk + 3][lm] = av.w;
        Bs[lk + 0][lm] = bv.x; Bs[lk + 1][lm] = bv.y; Bs[lk + 2][lm] = bv.z; Bs[lk + 3][lm] = bv.w;
        __syncthreads();
#pragma unroll
        for (int kk = 0; kk < 16; kk++) {
            float ar[4], br[4];
#pragma unroll
            for (int i = 0; i < 4; i++) { ar[i] = As[kk][ty * 4 + i]; br[i] = Bs[kk][tx * 4 + i]; }
#pragma unroll
            for (int i = 0; i < 4; i++)
#pragma unroll
                for (int j = 0; j < 4; j++) acc[i][j] += ar[i] * br[j];
        }
        __syncthreads();
    }
#pragma unroll
    for (int i = 0; i < 4; i++)
#pragma unroll
        for (int j = 0; j < 4; j++)
            d_L2[(size_t)(I + ty * 4 + i) * Nn + J + tx * 4 + j] = acc[i][j];
    if (blockIdx.y != blockIdx.x) {
        // mirror transposed tile
#pragma unroll
        for (int i = 0; i < 4; i++)
#pragma unroll
            for (int j = 0; j < 4; j++)
                Ts[tx * 4 + j][ty * 4 + i] = acc[i][j];
        __syncthreads();
        for (int idx = t; idx < 64 * 64; idx += 256) {
            int r = idx >> 6, c = idx & 63;
            d_L2[(size_t)(J + r) * Nn + I + c] = Ts[r][c];
        }
    }
}

// ---------------- Ht[e, :] = w0*b_e + w1*(L[h,:]-L[t,:]) + w2*(L2[h,:]-L2[t,:]) ----------------
__global__ void k_buildHt() {
    int e = blockIdx.x;
    int h = d_heads[e], tt = d_tails[e];
    float w0 = d_w0[e], w1 = d_w1[e], w2 = d_w2[e];
    const float* Lh  = &d_L [(size_t)h  * Nn];
    const float* Lt  = &d_L [(size_t)tt * Nn];
    const float* L2h = &d_L2[(size_t)h  * Nn];
    const float* L2t = &d_L2[(size_t)tt * Nn];
    float* out = &d_Ht[(size_t)e * Nn];
    for (int n = threadIdx.x; n < Nn; n += 256) {
        float v = w1 * (Lh[n] - Lt[n]) + w2 * (L2h[n] - L2t[n]);
        if (n == h)  v += w0;
        if (n == tt) v -= w0;
        out[n] = v;
    }
}

// ---------------- S = H diag(sigma) H^T + C_w  (lower-triangle tiles only) ----------------
__global__ void k_gemmS(const float* __restrict__ Cw) {
    if (blockIdx.y < blockIdx.x) return;   // only I >= J
    __shared__ float As[16][64], Bs[16][64];
    int I = blockIdx.y * 64, J = blockIdx.x * 64;
    int t = threadIdx.x;
    int ldk = t >> 4, ldm = (t & 15) << 2;
    int ty = t >> 4, tx = t & 15;
    float acc[4][4] = {};
    for (int e0 = 0; e0 < Ee; e0 += 16) {
        float sg = d_sigma[e0 + ldk];
        const float* row = &d_Ht[(size_t)(e0 + ldk) * Nn];
        float4 av = *(const float4*)&row[I + ldm];
        float4 bv = *(const float4*)&row[J + ldm];
        av.x *= sg; av.y *= sg; av.z *= sg; av.w *= sg;
        *(float4*)&As[ldk][ldm] = av;
        *(float4*)&Bs[ldk][ldm] = bv;
        __syncthreads();
#pragma unroll
        for (int kk = 0; kk < 16; kk++) {
            float4 a4 = *(const float4*)&As[kk][ty * 4];
            float4 b4 = *(const float4*)&Bs[kk][tx * 4];
            float ar[4] = {a4.x, a4.y, a4.z, a4.w};
            float br[4] = {b4.x, b4.y, b4.z, b4.w};
#pragma unroll
            for (int i = 0; i < 4; i++)
#pragma unroll
                for (int j = 0; j < 4; j++) acc[i][j] += ar[i] * br[j];
        }
        __syncthreads();
    }
#pragma unroll
    for (int i = 0; i < 4; i++)
#pragma unroll
        for (int j = 0; j < 4; j++) {
            size_t idx = (size_t)(I + ty * 4 + i) * Nn + J + tx * 4 + j;
            d_S[idx] = acc[i][j] + Cw[idx];
        }
}

// ---------------- parallel 64x64 Cholesky factor + triangular inverse ----------------
__global__ void k_potrf(int kblk) {
    int o = kblk * NB;
    __shared__ float A[NB][NB + 1];
    __shared__ float Bi[NB][NB + 1];
    int t = threadIdx.x;   // 256 threads
    for (int idx = t; idx < NB * NB; idx += 256) {
        int r = idx >> 6, c = idx & 63;
        A[r][c] = d_S[(size_t)(o + r) * Nn + o + c];
        Bi[r][c] = (r == c) ? 1.f : 0.f;
    }
    __syncthreads();
    for (int k = 0; k < NB; k++) {
        if (t == 0) A[k][k] = sqrtf(A[k][k]);
        __syncthreads();
        float inv = 1.f / A[k][k];
        if (t < NB) {
            if (t > k) A[t][k] *= inv;      // scale column k of factor
            Bi[k][t] *= inv;                // scale row k of inverse
        }
        __syncthreads();
        // live strip: rows r > k. one FMA per element:
        //   c <= k      -> inverse update
        //   k < c <= r  -> factor rank-1 update
        for (int idx = (k + 1) * NB + t; idx < NB * NB; idx += 256) {
            int r = idx >> 6, c = idx & 63;
            float lrk = A[r][k];
            if (c <= k)          Bi[r][c] -= lrk * Bi[k][c];
            else if (c <= r)     A[r][c]  -= lrk * A[c][k];
        }
        __syncthreads();
    }
    for (int idx = t; idx < NB * NB; idx += 256) {
        int r = idx >> 6, c = idx & 63;
        d_S[(size_t)(o + r) * Nn + o + c] = A[r][c];
        d_Linv[kblk * NB * NB + idx] = Bi[r][c];
    }
}

// panel rows: L21 = A21 * Linv^T (in place)
__global__ void k_trsm(int kblk) {
    int o = kblk * NB;
    int r0 = o + NB + blockIdx.x * NB;
    __shared__ float At[NB][NB + 1], Lv[NB][NB + 1];
    int t = threadIdx.x;
    for (int idx = t; idx < NB * NB; idx += 256) {
        int r = idx >> 6, c = idx & 63;
        At[r][c] = d_S[(size_t)(r0 + r) * Nn + o + c];
        Lv[r][c] = d_Linv[kblk * NB * NB + idx];
    }
    __syncthreads();
    int ty = t >> 4, tx = t & 15;
    float acc[4][4] = {};
    for (int m = 0; m < NB; m++) {
        float ar[4], br[4];
#pragma unroll
        for (int i = 0; i < 4; i++) { ar[i] = At[ty * 4 + i][m]; br[i] = Lv[tx * 4 + i][m]; }
#pragma unroll
        for (int i = 0; i < 4; i++)
#pragma unroll
            for (int j = 0; j < 4; j++) acc[i][j] += ar[i] * br[j];
    }
#pragma unroll
    for (int i = 0; i < 4; i++)
#pragma unroll
        for (int j = 0; j < 4; j++)
            d_S[(size_t)(r0 + ty * 4 + i) * Nn + o + tx * 4 + j] = acc[i][j];
}

// trailing update: A22 -= L21 * L21^T (lower tiles only)
__global__ void k_syrk(int kblk) {
    int bi = blockIdx.y, bj = blockIdx.x;
    if (bi < bj) return;
    int o = kblk * NB;
    int ri = o + NB + bi * NB, rj = o + NB + bj * NB;
    __shared__ float Pi[NB][NB + 1], Pj[NB][NB + 1];
    int t = threadIdx.x;
    for (int idx = t; idx < NB * NB; idx += 256) {
        int r = idx >> 6, c = idx & 63;
        Pi[r][c] = d_S[(size_t)(ri + r) * Nn + o + c];
        Pj[r][c] = d_S[(size_t)(rj + r) * Nn + o + c];
    }
    __syncthreads();
    int ty = t >> 4, tx = t & 15;
    float acc[4][4] = {};
    for (int m = 0; m < NB; m++) {
        float ar[4], br[4];
#pragma unroll
        for (int i = 0; i < 4; i++) { ar[i] = Pi[ty * 4 + i][m]; br[i] = Pj[tx * 4 + i][m]; }
#pragma unroll
        for (int i = 0; i < 4; i++)
#pragma unroll
            for (int j = 0; j < 4; j++) acc[i][j] += ar[i] * br[j];
    }
#pragma unroll
    for (int i = 0; i < 4; i++)
#pragma unroll
        for (int j = 0; j < 4; j++) {
            size_t idx = (size_t)(ri + ty * 4 + i) * Nn + rj + tx * 4 + j;
            d_S[idx] -= acc[i][j];
        }
}

// ---------------- fused forward solve: L y = r (single block, all panels) ----------------
__global__ void k_fsolve_all() {
    __shared__ float yv[Nn];
    __shared__ float part[NB];
    __shared__ float tv[NB];
    int t = threadIdx.x, lane = t & 31, w = t >> 5;   // 1024 threads, 32 warps
    for (int k = 0; k < NKB; k++) {
        int o = k * NB;
        int row0 = w, row1 = w + 32;
        const float* S0 = &d_S[(size_t)(o + row0) * Nn];
        const float* S1 = &d_S[(size_t)(o + row1) * Nn];
        float r0 = 0.f, r1 = 0.f;
        for (int j = lane; j < o; j += 32) {
            float yj = yv[j];
            r0 += S0[j] * yj;
            r1 += S1[j] * yj;
        }
        for (int off = 16; off; off >>= 1) {
            r0 += __shfl_down_sync(0xffffffffu, r0, off);
            r1 += __shfl_down_sync(0xffffffffu, r1, off);
        }
        if (lane == 0) { part[row0] = r0; part[row1] = r1; }
        __syncthreads();
        if (t < NB) tv[t] = d_r[o + t] - part[t];
        __syncthreads();
        if (t < NB) {
            const float* Li = &d_Linv[k * NB * NB + t * NB];
            float acc = 0.f;
#pragma unroll
            for (int m = 0; m < NB; m++) acc += Li[m] * tv[m];
            yv[o + t] = acc;
        }
        __syncthreads();
    }
    if (t < Nn) d_yv[t] = yv[t];
}

// ---------------- fused backward solve: L^T z = y (single block) ----------------
__global__ void k_bsolve_all() {
    __shared__ float zs[Nn];
    __shared__ float Ts[NB][NB + 1];
    __shared__ float pr[16][NB];
    __shared__ float tv[NB];
    int t = threadIdx.x;               // 1024 threads
    int g = t >> 6, i = t & 63;        // 16 groups of 64
    int lr = t >> 4, lc = (t & 15) * 4;
    for (int k = NKB - 1; k >= 0; k--) {
        int o = k * NB;
        float acc = 0.f;
        for (int rb = k + 1; rb < NKB; rb++) {
            __syncthreads();           // protect previous Ts consumers
            float4 v = *(const float4*)&d_S[(size_t)(rb * NB + lr) * Nn + o + lc];
            Ts[lr][lc + 0] = v.x; Ts[lr][lc + 1] = v.y; Ts[lr][lc + 2] = v.z; Ts[lr][lc + 3] = v.w;
            __syncthreads();
#pragma unroll
            for (int rr4 = 0; rr4 < 4; rr4++) {
                int rr = g * 4 + rr4;
                acc += Ts[rr][i] * zs[rb * NB + rr];
            }
        }
        pr[g][i] = acc;
        __syncthreads();
        if (t < NB) {
            float s = 0.f;
#pragma unroll
            for (int gg = 0; gg < 16; gg++) s += pr[gg][t];
            tv[t] = d_yv[o + t] - s;
        }
        __syncthreads();
        // load Linv tile into Ts (reuse), then z = Linv^T tv
        {
            const float* Li = &d_Linv[k * NB * NB];
            Ts[lr][lc + 0] = Li[lr * NB + lc + 0];
            Ts[lr][lc + 1] = Li[lr * NB + lc + 1];
            Ts[lr][lc + 2] = Li[lr * NB + lc + 2];
            Ts[lr][lc + 3] = Li[lr * NB + lc + 3];
        }
        __syncthreads();
        if (t < NB) {
            float acc2 = 0.f;
#pragma unroll
            for (int m = 0; m < NB; m++) acc2 += Ts[m][t] * tv[m];
            zs[o + t] = acc2;
        }
        __syncthreads();
    }
    if (t < Nn) d_z[t] = zs[t];
}

// out[e] = relu(s[e] + sigma[e] * dot(Ht[e,:], z))
__global__ void k_out(float* __restrict__ out) {
    int warp = (blockIdx.x << 3) + (threadIdx.x >> 5);
    int lane = threadIdx.x & 31;
    if (warp >= Ee) return;
    const float* row = &d_Ht[(size_t)warp * Nn];
    float acc = 0.f;
    for (int n = lane; n < Nn; n += 32) acc += row[n] * d_z[n];
    for (int off = 16; off; off >>= 1) acc += __shfl_down_sync(0xffffffffu, acc, off);
    if (lane == 0) {
        float v = d_s[warp] + d_sigma[warp] * acc;
        out[warp] = fmaxf(v, 0.f);
    }
}

// ---------------- launch ----------------
extern "C" void kernel_launch(void* const* d_in, const int* in_sizes, int n_in,
                              void* d_out, int out_size) {
    (void)in_sizes; (void)n_in; (void)out_size;
    const float* F  = (const float*)d_in[0];
    const float* B  = (const float*)d_in[1];
    const float* Cu = (const float*)d_in[2];
    const float* Cw = (const float*)d_in[3];
    const float* Cx = (const float*)d_in[4];
    const float* s0 = (const float*)d_in[5];
    const float* a  = (const float*)d_in[6];
    const float* q  = (const float*)d_in[7];
    const float* y  = (const float*)d_in[8];
    float* out = (float*)d_out;

    k_extract<<<(Nn * Ee + 255) / 256, 256>>>(B);
    k_init<<<(Nn * Nn + 255) / 256, 256>>>(F, Cu, Cx, s0, q);
    k_assemble<<<(Ee + 255) / 256, 256>>>();
    k_matvec<<<Nn, 128>>>(0, 1);
    k_matvec<<<Nn, 128>>>(1, 2);
    k_matvec<<<Nn, 128>>>(2, 3);
    k_VWpoly<<<(Ee + 255) / 256, 256>>>(a, y);
    k_gemmL2<<<dim3(16, 16), 256>>>();
    k_buildHt<<<Ee, 256>>>();
    k_gemmS<<<dim3(16, 16), 256>>>(Cw);

    for (int k = 0; k < NKB; k++) {
        k_potrf<<<1, 256>>>(k);
        int rb = (Nn - (k + 1) * NB) / NB;
        if (rb > 0) {
            k_trsm<<<rb, 256>>>(k);
            k_syrk<<<dim3(rb, rb), 256>>>(k);
        }
    }
    k_fsolve_all<<<1, 1024>>>();
    k_bsolve_all<<<1, 1024>>>();

    k_out<<<Ee / 8, 256>>>(out);
}